// round 3
// baseline (speedup 1.0000x reference)
#include <cuda_runtime.h>
#include <cstdint>

// Problem constants (fixed by the dataset)
#define N_NODES 100000
#define N_EDGES 800000
#define IN_SIZE 128
#define OUT_SIZE 64

// ---------------------------------------------------------------------------
// Scratch (no cudaMalloc allowed)
// ---------------------------------------------------------------------------
__device__ int   g_is64;
__device__ int   g_src32[N_EDGES];
__device__ int   g_tgt32[N_EDGES];
__device__ int   g_rowptr[N_NODES + 1];
__device__ __align__(16) float g_buf0[(size_t)N_NODES * OUT_SIZE];
__device__ __align__(16) float g_buf1[(size_t)N_NODES * OUT_SIZE];

// packed f32x2 FMA: a = x * w + a (elementwise on both 32-bit halves)
__device__ __forceinline__ void ffma2(unsigned long long& a,
                                      unsigned long long x,
                                      unsigned long long w) {
    asm("fma.rn.f32x2 %0, %1, %2, %0;" : "+l"(a) : "l"(x), "l"(w));
}

// ---------------------------------------------------------------------------
// 1) Detect whether index buffers are int64 or int32.
// ---------------------------------------------------------------------------
__global__ void detect_kernel(const void* src_any) {
    if (threadIdx.x == 0) {
        const long long* p = (const long long*)src_any;
        int is64 = 1;
        for (int i = 0; i < 32; ++i) {
            long long v = p[i];
            if (v < 0 || v >= (long long)N_NODES) { is64 = 0; break; }
        }
        g_is64 = is64;
    }
}

// ---------------------------------------------------------------------------
// 2) Normalize indices to int32 scratch.
// ---------------------------------------------------------------------------
__global__ void convert_kernel(const void* src_any, const void* tgt_any) {
    int i = blockIdx.x * blockDim.x + threadIdx.x;
    if (i >= N_EDGES) return;
    if (g_is64) {
        g_src32[i] = (int)((const long long*)src_any)[i];
        g_tgt32[i] = (int)((const long long*)tgt_any)[i];
    } else {
        g_src32[i] = ((const int*)src_any)[i];
        g_tgt32[i] = ((const int*)tgt_any)[i];
    }
}

// ---------------------------------------------------------------------------
// 3) row_ptr via per-node lower_bound in the sorted tgt array.
// ---------------------------------------------------------------------------
__global__ void rowptr_kernel() {
    int t = blockIdx.x * blockDim.x + threadIdx.x;
    if (t > N_NODES) return;
    int lo = 0, hi = N_EDGES;
    while (lo < hi) {
        int mid = (lo + hi) >> 1;
        if (g_tgt32[mid] < t) lo = mid + 1; else hi = mid;
    }
    g_rowptr[t] = lo;
}

// ---------------------------------------------------------------------------
// 4) GEMM: Y = X @ W + b   (100000x128 @ 128x64, fp32) with packed FFMA2.
//    Block: 256 rows x 64 cols. Thread tile: 8 rows x 8 cols held as
//    4 packed row-pairs (f32x2) x 8 cols. X staged transposed in smem so
//    ulonglong2 reads give natural (row2i, row2i+1) packs. W staged
//    DUPLICATED (w_j,w_j,...) so a 64-bit read gives the (w_j,w_j) operand.
//    Per thread per k: 6 LDS.128 + 32 FFMA2 (= 64 fp32 FMA).
// ---------------------------------------------------------------------------
__global__ __launch_bounds__(256, 2) void gemm_kernel(const float* __restrict__ X,
                                                      const float* __restrict__ W,
                                                      const float* __restrict__ b) {
    __shared__ float XsT[16][260];   // [k][row], pad 256->260 (16B-aligned rows)
    __shared__ float Wd[16][128];    // [k][2*col] duplicated: w0,w0,w1,w1,...

    const int tid = threadIdx.x;
    const int tr  = tid >> 3;        // 0..31  -> rows tr*8 .. tr*8+7
    const int tc  = tid & 7;         // 0..7   -> cols tc*8 .. tc*8+7
    const int rowBase = blockIdx.x * 256;

    // gmem-load mapping for X: thread covers 4 rows (lr + 64p), 16B k-chunk lk
    const int lr = tid >> 2;         // 0..63
    const int lk = (tid & 3) << 2;   // 0,4,8,12

    // W tile load mapping: float4 per thread
    const int wk = tid >> 4;          // 0..15
    const int wc = (tid & 15) << 2;   // 0..60

    unsigned long long acc[4][8];
    #pragma unroll
    for (int i = 0; i < 4; ++i)
        #pragma unroll
        for (int j = 0; j < 8; ++j) acc[i][j] = 0ULL;

    float4 xreg[4];
    float4 wreg;

    // prefetch k-tile 0
    #pragma unroll
    for (int p = 0; p < 4; ++p) {
        const int r = rowBase + lr + 64 * p;
        xreg[p] = (r < N_NODES) ? *(const float4*)&X[(size_t)r * IN_SIZE + lk]
                                : make_float4(0.f, 0.f, 0.f, 0.f);
    }
    wreg = *(const float4*)&W[(size_t)wk * OUT_SIZE + wc];

    for (int kt = 0; kt < IN_SIZE / 16; ++kt) {
        __syncthreads();
        // stage X transposed
        #pragma unroll
        for (int p = 0; p < 4; ++p) {
            const int r = lr + 64 * p;
            XsT[lk + 0][r] = xreg[p].x;
            XsT[lk + 1][r] = xreg[p].y;
            XsT[lk + 2][r] = xreg[p].z;
            XsT[lk + 3][r] = xreg[p].w;
        }
        // stage W duplicated
        *(float4*)&Wd[wk][2 * wc]     = make_float4(wreg.x, wreg.x, wreg.y, wreg.y);
        *(float4*)&Wd[wk][2 * wc + 4] = make_float4(wreg.z, wreg.z, wreg.w, wreg.w);
        __syncthreads();

        // prefetch next k-tile
        if (kt < IN_SIZE / 16 - 1) {
            const int kc = (kt + 1) * 16;
            #pragma unroll
            for (int p = 0; p < 4; ++p) {
                const int r = rowBase + lr + 64 * p;
                xreg[p] = (r < N_NODES) ? *(const float4*)&X[(size_t)r * IN_SIZE + kc + lk]
                                        : make_float4(0.f, 0.f, 0.f, 0.f);
            }
            wreg = *(const float4*)&W[(size_t)(kc + wk) * OUT_SIZE + wc];
        }

        #pragma unroll
        for (int k = 0; k < 16; ++k) {
            // 4 packed row-pairs: rows tr*8 .. tr*8+7
            const ulonglong2 xa = *(const ulonglong2*)&XsT[k][tr * 8];
            const ulonglong2 xb = *(const ulonglong2*)&XsT[k][tr * 8 + 4];
            // 8 packed (w_j, w_j) operands: cols tc*8 .. tc*8+7
            const ulonglong2 wa = *(const ulonglong2*)&Wd[k][tc * 16];
            const ulonglong2 wb = *(const ulonglong2*)&Wd[k][tc * 16 + 4];
            const ulonglong2 wc2 = *(const ulonglong2*)&Wd[k][tc * 16 + 8];
            const ulonglong2 wd = *(const ulonglong2*)&Wd[k][tc * 16 + 12];
            const unsigned long long xp[4] = {xa.x, xa.y, xb.x, xb.y};
            const unsigned long long wp[8] = {wa.x, wa.y, wb.x, wb.y,
                                              wc2.x, wc2.y, wd.x, wd.y};
            #pragma unroll
            for (int i = 0; i < 4; ++i)
                #pragma unroll
                for (int j = 0; j < 8; ++j)
                    ffma2(acc[i][j], xp[i], wp[j]);
        }
    }

    // epilogue: unpack row-pairs, add bias, store float4s
    const float4 b0 = *(const float4*)&b[tc * 8];
    const float4 b1 = *(const float4*)&b[tc * 8 + 4];
    const float bias[8] = {b0.x, b0.y, b0.z, b0.w, b1.x, b1.y, b1.z, b1.w};
    #pragma unroll
    for (int i = 0; i < 4; ++i) {
        const int r0 = rowBase + tr * 8 + 2 * i;
        float lo[8], hi[8];
        #pragma unroll
        for (int j = 0; j < 8; ++j) {
            lo[j] = __uint_as_float((unsigned)(acc[i][j] & 0xffffffffULL)) + bias[j];
            hi[j] = __uint_as_float((unsigned)(acc[i][j] >> 32)) + bias[j];
        }
        if (r0 < N_NODES) {
            *(float4*)&g_buf0[(size_t)r0 * OUT_SIZE + tc * 8] =
                make_float4(lo[0], lo[1], lo[2], lo[3]);
            *(float4*)&g_buf0[(size_t)r0 * OUT_SIZE + tc * 8 + 4] =
                make_float4(lo[4], lo[5], lo[6], lo[7]);
        }
        if (r0 + 1 < N_NODES) {
            *(float4*)&g_buf0[(size_t)(r0 + 1) * OUT_SIZE + tc * 8] =
                make_float4(hi[0], hi[1], hi[2], hi[3]);
            *(float4*)&g_buf0[(size_t)(r0 + 1) * OUT_SIZE + tc * 8 + 4] =
                make_float4(hi[4], hi[5], hi[6], hi[7]);
        }
    }
}

// ---------------------------------------------------------------------------
// 5) Propagation: one warp per node.
//    new[t] = (deg>0) ? (in[t] + sum_{e in seg(t)} in[src[e]]) / (deg+1) : 0
// ---------------------------------------------------------------------------
__global__ __launch_bounds__(256) void prop_kernel(float* __restrict__ dout, int stage) {
    const int gw   = (blockIdx.x * blockDim.x + threadIdx.x) >> 5;
    const int lane = threadIdx.x & 31;
    if (gw >= N_NODES) return;
    const int t = gw;

    const float2* __restrict__ in2  = (stage == 0) ? (const float2*)g_buf0 : (const float2*)g_buf1;
    float2*       __restrict__ out2 = (stage == 0) ? (float2*)g_buf1       : (float2*)dout;

    const int start = g_rowptr[t];
    const int end   = g_rowptr[t + 1];
    const int deg   = end - start;

    if (deg == 0) {
        out2[t * 32 + lane] = make_float2(0.f, 0.f);
        return;
    }

    float2 acc = make_float2(0.f, 0.f);
    int e = start;
    for (; e + 4 <= end; e += 4) {
        const int s0 = __ldg(&g_src32[e + 0]);
        const int s1 = __ldg(&g_src32[e + 1]);
        const int s2 = __ldg(&g_src32[e + 2]);
        const int s3 = __ldg(&g_src32[e + 3]);
        const float2 v0 = __ldg(&in2[s0 * 32 + lane]);
        const float2 v1 = __ldg(&in2[s1 * 32 + lane]);
        const float2 v2 = __ldg(&in2[s2 * 32 + lane]);
        const float2 v3 = __ldg(&in2[s3 * 32 + lane]);
        acc.x += (v0.x + v1.x) + (v2.x + v3.x);
        acc.y += (v0.y + v1.y) + (v2.y + v3.y);
    }
    for (; e < end; ++e) {
        const int s = __ldg(&g_src32[e]);
        const float2 v = __ldg(&in2[s * 32 + lane]);
        acc.x += v.x; acc.y += v.y;
    }

    const float2 own = __ldg(&in2[t * 32 + lane]);
    const float sc = 1.0f / (float)(deg + 1);
    float2 r = make_float2((acc.x + own.x) * sc, (acc.y + own.y) * sc);
    if (stage == 1) { r.x = fmaxf(r.x, 0.f); r.y = fmaxf(r.y, 0.f); }
    out2[t * 32 + lane] = r;
}

// ---------------------------------------------------------------------------
// Launch. Inputs (metadata order): data, W, b, src_idx, tgt_idx
// ---------------------------------------------------------------------------
extern "C" void kernel_launch(void* const* d_in, const int* in_sizes, int n_in,
                              void* d_out, int out_size) {
    const float* X = (const float*)d_in[0];
    const float* W = (const float*)d_in[1];
    const float* b = (const float*)d_in[2];
    const void*  src = d_in[3];
    const void*  tgt = d_in[4];
    float* out = (float*)d_out;

    detect_kernel<<<1, 32>>>(src);
    convert_kernel<<<(N_EDGES + 255) / 256, 256>>>(src, tgt);
    rowptr_kernel<<<(N_NODES + 1 + 255) / 256, 256>>>();
    gemm_kernel<<<(N_NODES + 255) / 256, 256>>>(X, W, b);
    const int propBlocks = (N_NODES * 32 + 255) / 256;  // 1 warp/node
    prop_kernel<<<propBlocks, 256>>>(out, 0);
    prop_kernel<<<propBlocks, 256>>>(out, 1);
}

// round 6
// speedup vs baseline: 1.6506x; 1.6506x over previous
#include <cuda_runtime.h>
#include <cuda_fp16.h>
#include <cstdint>

// Problem constants (fixed by the dataset)
#define N_NODES 100000
#define N_EDGES 800000
#define IN_SIZE 128
#define OUT_SIZE 64

// ---------------------------------------------------------------------------
// Scratch (no cudaMalloc allowed)
// ---------------------------------------------------------------------------
__device__ int   g_is64;
__device__ int   g_src32[N_EDGES];
__device__ int   g_tgt32[N_EDGES];
__device__ int   g_rowptr[N_NODES + 1];
// fp16 intermediate activations: [node][32] half2  (64 cols)
__device__ __align__(16) __half2 g_h0[(size_t)N_NODES * 32];
__device__ __align__(16) __half2 g_h1[(size_t)N_NODES * 32];

// ---------------------------------------------------------------------------
// 1) Detect int64 vs int32 indices (warp-parallel, one ballot).
//    int32 data read as int64 pairs two uniform values in [0,1e5): the high
//    word is nonzero w.p. 1-1e-5 per element -> out-of-range almost surely.
// ---------------------------------------------------------------------------
__global__ void detect_kernel(const void* src_any) {
    const long long v = ((const long long*)src_any)[threadIdx.x & 31];
    const bool ok = (v >= 0 && v < (long long)N_NODES);
    const unsigned m = __ballot_sync(0xffffffffu, ok);
    if (threadIdx.x == 0) g_is64 = (m == 0xffffffffu) ? 1 : 0;
}

// ---------------------------------------------------------------------------
// 2) Normalize indices to int32 scratch.
// ---------------------------------------------------------------------------
__global__ void convert_kernel(const void* src_any, const void* tgt_any) {
    int i = blockIdx.x * blockDim.x + threadIdx.x;
    if (i >= N_EDGES) return;
    if (g_is64) {
        g_src32[i] = (int)((const long long*)src_any)[i];
        g_tgt32[i] = (int)((const long long*)tgt_any)[i];
    } else {
        g_src32[i] = ((const int*)src_any)[i];
        g_tgt32[i] = ((const int*)tgt_any)[i];
    }
}

// ---------------------------------------------------------------------------
// 3) row_ptr via per-node lower_bound in the sorted tgt array.
// ---------------------------------------------------------------------------
__global__ void rowptr_kernel() {
    int t = blockIdx.x * blockDim.x + threadIdx.x;
    if (t > N_NODES) return;
    int lo = 0, hi = N_EDGES;
    while (lo < hi) {
        int mid = (lo + hi) >> 1;
        if (g_tgt32[mid] < t) lo = mid + 1; else hi = mid;
    }
    g_rowptr[t] = lo;
}

// ---------------------------------------------------------------------------
// 4) GEMM: Y = X @ W + b  (100000x128 @ 128x64, fp32 math) -> fp16 store.
//    Identical mainloop to the R2 register-tiled kernel (measured at 92% of
//    the scalar FFMA issue floor); only the epilogue converts to half2.
// ---------------------------------------------------------------------------
__global__ __launch_bounds__(256, 2) void gemm_kernel(const float* __restrict__ X,
                                                      const float* __restrict__ W,
                                                      const float* __restrict__ b) {
    __shared__ float XsT[16][260];   // [k][row], pad 256->260
    __shared__ float Ws[16][64];     // [k][col]

    const int tid = threadIdx.x;
    const int tr  = tid >> 3;        // 0..31  -> rows tr*8 .. tr*8+7
    const int tc  = tid & 7;         // 0..7   -> cols tc*8 .. tc*8+7
    const int rowBase = blockIdx.x * 256;

    const int lr = tid >> 2;         // 0..63
    const int lk = (tid & 3) << 2;   // 0,4,8,12

    const int wk = tid >> 4;          // 0..15
    const int wc = (tid & 15) << 2;   // 0..60

    float acc[8][8];
    #pragma unroll
    for (int i = 0; i < 8; ++i)
        #pragma unroll
        for (int j = 0; j < 8; ++j) acc[i][j] = 0.f;

    float4 xreg[4];
    float4 wreg;

    #pragma unroll
    for (int p = 0; p < 4; ++p) {
        const int r = rowBase + lr + 64 * p;
        xreg[p] = (r < N_NODES) ? *(const float4*)&X[(size_t)r * IN_SIZE + lk]
                                : make_float4(0.f, 0.f, 0.f, 0.f);
    }
    wreg = *(const float4*)&W[(size_t)wk * OUT_SIZE + wc];

    for (int kt = 0; kt < IN_SIZE / 16; ++kt) {
        __syncthreads();
        #pragma unroll
        for (int p = 0; p < 4; ++p) {
            const int r = lr + 64 * p;
            XsT[lk + 0][r] = xreg[p].x;
            XsT[lk + 1][r] = xreg[p].y;
            XsT[lk + 2][r] = xreg[p].z;
            XsT[lk + 3][r] = xreg[p].w;
        }
        *(float4*)&Ws[wk][wc] = wreg;
        __syncthreads();

        if (kt < IN_SIZE / 16 - 1) {
            const int kc = (kt + 1) * 16;
            #pragma unroll
            for (int p = 0; p < 4; ++p) {
                const int r = rowBase + lr + 64 * p;
                xreg[p] = (r < N_NODES) ? *(const float4*)&X[(size_t)r * IN_SIZE + kc + lk]
                                        : make_float4(0.f, 0.f, 0.f, 0.f);
            }
            wreg = *(const float4*)&W[(size_t)(kc + wk) * OUT_SIZE + wc];
        }

        #pragma unroll
        for (int k = 0; k < 16; ++k) {
            const float4 xa = *(const float4*)&XsT[k][tr * 8];
            const float4 xb = *(const float4*)&XsT[k][tr * 8 + 4];
            const float4 wa = *(const float4*)&Ws[k][tc * 8];
            const float4 wb = *(const float4*)&Ws[k][tc * 8 + 4];
            const float xv[8] = {xa.x, xa.y, xa.z, xa.w, xb.x, xb.y, xb.z, xb.w};
            const float wv[8] = {wa.x, wa.y, wa.z, wa.w, wb.x, wb.y, wb.z, wb.w};
            #pragma unroll
            for (int i = 0; i < 8; ++i)
                #pragma unroll
                for (int j = 0; j < 8; ++j)
                    acc[i][j] += xv[i] * wv[j];
        }
    }

    // epilogue: add bias, convert to fp16, one 16B store per row
    const float4 b0 = *(const float4*)&b[tc * 8];
    const float4 b1 = *(const float4*)&b[tc * 8 + 4];
    #pragma unroll
    for (int i = 0; i < 8; ++i) {
        const int r = rowBase + tr * 8 + i;
        if (r < N_NODES) {
            __align__(16) __half2 hv[4];
            hv[0] = __floats2half2_rn(acc[i][0] + b0.x, acc[i][1] + b0.y);
            hv[1] = __floats2half2_rn(acc[i][2] + b0.z, acc[i][3] + b0.w);
            hv[2] = __floats2half2_rn(acc[i][4] + b1.x, acc[i][5] + b1.y);
            hv[3] = __floats2half2_rn(acc[i][6] + b1.z, acc[i][7] + b1.w);
            *(uint4*)&g_h0[(size_t)r * 32 + tc * 4] = *(const uint4*)hv;
        }
    }
}

__device__ __forceinline__ float2 h2f(__half2 h) { return __half22float2(h); }

// ---------------------------------------------------------------------------
// 5) Propagation: one warp per node; lane owns cols (2*lane, 2*lane+1).
//    Gathers fp16 rows (128 B/edge), accumulates fp32.
//    new[t] = (deg>0) ? (in[t] + sum in[src[e]]) / (deg+1) : 0
//    stage 0: g_h0 -> g_h1 (fp16);  stage 1: g_h1 -> d_out (fp32, ReLU)
// ---------------------------------------------------------------------------
__global__ __launch_bounds__(256) void prop_kernel(float* __restrict__ dout, int stage) {
    const int gw   = (blockIdx.x * blockDim.x + threadIdx.x) >> 5;
    const int lane = threadIdx.x & 31;
    if (gw >= N_NODES) return;
    const int t = gw;

    const __half2* __restrict__ in = (stage == 0) ? g_h0 : g_h1;

    const int start = g_rowptr[t];
    const int end   = g_rowptr[t + 1];
    const int deg   = end - start;

    if (deg == 0) {
        if (stage == 0) g_h1[(size_t)t * 32 + lane] = __floats2half2_rn(0.f, 0.f);
        else            ((float2*)dout)[(size_t)t * 32 + lane] = make_float2(0.f, 0.f);
        return;
    }

    float2 acc = make_float2(0.f, 0.f);
    int e = start;
    for (; e + 4 <= end; e += 4) {
        const int s0 = __ldg(&g_src32[e + 0]);
        const int s1 = __ldg(&g_src32[e + 1]);
        const int s2 = __ldg(&g_src32[e + 2]);
        const int s3 = __ldg(&g_src32[e + 3]);
        const float2 v0 = h2f(in[(size_t)s0 * 32 + lane]);
        const float2 v1 = h2f(in[(size_t)s1 * 32 + lane]);
        const float2 v2 = h2f(in[(size_t)s2 * 32 + lane]);
        const float2 v3 = h2f(in[(size_t)s3 * 32 + lane]);
        acc.x += (v0.x + v1.x) + (v2.x + v3.x);
        acc.y += (v0.y + v1.y) + (v2.y + v3.y);
    }
    for (; e < end; ++e) {
        const int s = __ldg(&g_src32[e]);
        const float2 v = h2f(in[(size_t)s * 32 + lane]);
        acc.x += v.x; acc.y += v.y;
    }

    const float2 own = h2f(in[(size_t)t * 32 + lane]);
    const float sc = 1.0f / (float)(deg + 1);
    float2 r = make_float2((acc.x + own.x) * sc, (acc.y + own.y) * sc);
    if (stage == 0) {
        g_h1[(size_t)t * 32 + lane] = __floats2half2_rn(r.x, r.y);
    } else {
        r.x = fmaxf(r.x, 0.f); r.y = fmaxf(r.y, 0.f);
        ((float2*)dout)[(size_t)t * 32 + lane] = r;
    }
}

// ---------------------------------------------------------------------------
// Launch. Inputs (metadata order): data, W, b, src_idx, tgt_idx
// ---------------------------------------------------------------------------
extern "C" void kernel_launch(void* const* d_in, const int* in_sizes, int n_in,
                              void* d_out, int out_size) {
    const float* X = (const float*)d_in[0];
    const float* W = (const float*)d_in[1];
    const float* b = (const float*)d_in[2];
    const void*  src = d_in[3];
    const void*  tgt = d_in[4];
    float* out = (float*)d_out;

    detect_kernel<<<1, 32>>>(src);
    convert_kernel<<<(N_EDGES + 255) / 256, 256>>>(src, tgt);
    rowptr_kernel<<<(N_NODES + 1 + 255) / 256, 256>>>();
    gemm_kernel<<<(N_NODES + 255) / 256, 256>>>(X, W, b);
    const int propBlocks = (N_NODES * 32 + 255) / 256;  // 1 warp/node
    prop_kernel<<<propBlocks, 256>>>(out, 0);
    prop_kernel<<<propBlocks, 256>>>(out, 1);
}

// round 7
// speedup vs baseline: 2.1289x; 1.2898x over previous
#include <cuda_runtime.h>
#include <cuda_fp16.h>
#include <cstdint>

// Problem constants (fixed by the dataset)
#define N_NODES 100000
#define N_EDGES 800000
#define IN_SIZE 128
#define OUT_SIZE 64

// ---------------------------------------------------------------------------
// Scratch (no cudaMalloc allowed)
// ---------------------------------------------------------------------------
__device__ int   g_is64;
__device__ int   g_src32[N_EDGES];
__device__ int   g_tgt32[N_EDGES];
__device__ int   g_rowptr[N_NODES + 1];
// fp16 intermediate activations: [node][32] half2  (64 cols)
__device__ __align__(16) __half2 g_h0[(size_t)N_NODES * 32];
__device__ __align__(16) __half2 g_h1[(size_t)N_NODES * 32];

// ---------------------------------------------------------------------------
// 1) Detect int64 vs int32 indices (warp-parallel, one ballot).
// ---------------------------------------------------------------------------
__global__ void detect_kernel(const void* src_any) {
    const long long v = ((const long long*)src_any)[threadIdx.x & 31];
    const bool ok = (v >= 0 && v < (long long)N_NODES);
    const unsigned m = __ballot_sync(0xffffffffu, ok);
    if (threadIdx.x == 0) g_is64 = (m == 0xffffffffu) ? 1 : 0;
}

// ---------------------------------------------------------------------------
// 2) Normalize indices to int32 scratch.
// ---------------------------------------------------------------------------
__global__ void convert_kernel(const void* src_any, const void* tgt_any) {
    int i = blockIdx.x * blockDim.x + threadIdx.x;
    if (i >= N_EDGES) return;
    if (g_is64) {
        g_src32[i] = (int)((const long long*)src_any)[i];
        g_tgt32[i] = (int)((const long long*)tgt_any)[i];
    } else {
        g_src32[i] = ((const int*)src_any)[i];
        g_tgt32[i] = ((const int*)tgt_any)[i];
    }
}

// ---------------------------------------------------------------------------
// 3) row_ptr via per-node lower_bound in the sorted tgt array.
// ---------------------------------------------------------------------------
__global__ void rowptr_kernel() {
    int t = blockIdx.x * blockDim.x + threadIdx.x;
    if (t > N_NODES) return;
    int lo = 0, hi = N_EDGES;
    while (lo < hi) {
        int mid = (lo + hi) >> 1;
        if (g_tgt32[mid] < t) lo = mid + 1; else hi = mid;
    }
    g_rowptr[t] = lo;
}

// ---------------------------------------------------------------------------
// 4) GEMM via HMMA tensor cores: Y = X @ W + b -> fp16 store.
//    Block = 128 threads (4 warps), computes 128 rows x 64 cols, full K=128.
//    X tile 128x128 fp16 + W 128x64 fp16 staged in smem with 16B-chunk XOR
//    swizzle (chunk ^= row%8) -> conflict-free ldmatrix. Warp tile: 32x64
//    (2 x 8 m16n8k16 tiles, fp32 accum). A: ldmatrix.x4; B: ldmatrix.x4.trans.
// ---------------------------------------------------------------------------
#define XS_HALVES (128 * 128)   // 32768 B
#define WS_HALVES (128 * 64)    // 16384 B

__global__ __launch_bounds__(128) void gemm_kernel(const float* __restrict__ X,
                                                   const float* __restrict__ W,
                                                   const float* __restrict__ b) {
    __shared__ __half Xs[XS_HALVES];   // [row][k], swizzled chunks
    __shared__ __half Ws[WS_HALVES];   // [k][n],  swizzled chunks

    const int tid    = threadIdx.x;
    const int lane   = tid & 31;
    const int warpId = tid >> 5;
    const int rowBase = blockIdx.x * 128;

    // ---- stage X: 128x128 fp32 -> fp16, swizzled. 32 float4 per thread ----
    #pragma unroll
    for (int i = 0; i < 32; ++i) {
        const int linear = tid + 128 * i;      // 0..4095
        const int row = linear >> 5;           // 0..127
        const int c   = linear & 31;           // float4 col
        const int gr  = rowBase + row;
        float4 v = (gr < N_NODES) ? __ldg((const float4*)&X[(size_t)gr * IN_SIZE + 4 * c])
                                  : make_float4(0.f, 0.f, 0.f, 0.f);
        __align__(8) __half2 h[2];
        h[0] = __floats2half2_rn(v.x, v.y);
        h[1] = __floats2half2_rn(v.z, v.w);
        const int chunk = ((c >> 1) ^ (row & 7));          // 16B chunk swizzle
        *(uint2*)&Xs[row * 128 + chunk * 8 + 4 * (c & 1)] = *(const uint2*)h;
    }

    // ---- stage W: 128x64 fp32 -> fp16, swizzled. 16 float4 per thread ----
    #pragma unroll
    for (int i = 0; i < 16; ++i) {
        const int linear = tid + 128 * i;      // 0..2047
        const int k = linear >> 4;             // 0..127
        const int c = linear & 15;             // float4 col
        float4 v = __ldg((const float4*)&W[(size_t)k * OUT_SIZE + 4 * c]);
        __align__(8) __half2 h[2];
        h[0] = __floats2half2_rn(v.x, v.y);
        h[1] = __floats2half2_rn(v.z, v.w);
        const int chunk = ((c >> 1) ^ (k & 7));
        *(uint2*)&Ws[k * 64 + chunk * 8 + 4 * (c & 1)] = *(const uint2*)h;
    }
    __syncthreads();

    // ---- mma mainloop ----
    const int wr = warpId * 32;               // warp's local row base
    float d[2][8][4];
    #pragma unroll
    for (int rt = 0; rt < 2; ++rt)
        #pragma unroll
        for (int nt = 0; nt < 8; ++nt)
            #pragma unroll
            for (int q = 0; q < 4; ++q) d[rt][nt][q] = 0.f;

    #pragma unroll
    for (int ks = 0; ks < 8; ++ks) {
        // A fragments: 2 row-tiles of 16
        unsigned a[2][4];
        #pragma unroll
        for (int rt = 0; rt < 2; ++rt) {
            const int row = wr + rt * 16 + (lane & 15);            // lane%16
            const int chunk = (ks * 2 + (lane >> 4)) ^ (row & 7);
            const unsigned addr =
                (unsigned)__cvta_generic_to_shared(&Xs[row * 128 + chunk * 8]);
            asm volatile("ldmatrix.sync.aligned.m8n8.x4.shared.b16 {%0,%1,%2,%3}, [%4];"
                         : "=r"(a[rt][0]), "=r"(a[rt][1]), "=r"(a[rt][2]), "=r"(a[rt][3])
                         : "r"(addr));
        }
        // B fragments: 4 n-pairs of 16 cols, transposed load
        #pragma unroll
        for (int np = 0; np < 4; ++np) {
            const int k = ks * 16 + (lane & 7) + ((lane >> 3) & 1) * 8;
            const int chunk = (np * 2 + (lane >> 4)) ^ (k & 7);
            const unsigned addr =
                (unsigned)__cvta_generic_to_shared(&Ws[k * 64 + chunk * 8]);
            unsigned bf[4];
            asm volatile("ldmatrix.sync.aligned.m8n8.x4.trans.shared.b16 {%0,%1,%2,%3}, [%4];"
                         : "=r"(bf[0]), "=r"(bf[1]), "=r"(bf[2]), "=r"(bf[3])
                         : "r"(addr));
            #pragma unroll
            for (int rt = 0; rt < 2; ++rt) {
                asm volatile(
                    "mma.sync.aligned.m16n8k16.row.col.f32.f16.f16.f32 "
                    "{%0,%1,%2,%3}, {%4,%5,%6,%7}, {%8,%9}, {%0,%1,%2,%3};"
                    : "+f"(d[rt][2 * np][0]), "+f"(d[rt][2 * np][1]),
                      "+f"(d[rt][2 * np][2]), "+f"(d[rt][2 * np][3])
                    : "r"(a[rt][0]), "r"(a[rt][1]), "r"(a[rt][2]), "r"(a[rt][3]),
                      "r"(bf[0]), "r"(bf[1]));
                asm volatile(
                    "mma.sync.aligned.m16n8k16.row.col.f32.f16.f16.f32 "
                    "{%0,%1,%2,%3}, {%4,%5,%6,%7}, {%8,%9}, {%0,%1,%2,%3};"
                    : "+f"(d[rt][2 * np + 1][0]), "+f"(d[rt][2 * np + 1][1]),
                      "+f"(d[rt][2 * np + 1][2]), "+f"(d[rt][2 * np + 1][3])
                    : "r"(a[rt][0]), "r"(a[rt][1]), "r"(a[rt][2]), "r"(a[rt][3]),
                      "r"(bf[2]), "r"(bf[3]));
            }
        }
    }

    // ---- epilogue: bias + fp16 store ----
    float2 bias2[8];
    #pragma unroll
    for (int nt = 0; nt < 8; ++nt)
        bias2[nt] = __ldg(&((const float2*)b)[nt * 4 + (lane & 3)]);

    #pragma unroll
    for (int rt = 0; rt < 2; ++rt) {
        const int r0 = rowBase + wr + rt * 16 + (lane >> 2);
        const int r1 = r0 + 8;
        #pragma unroll
        for (int nt = 0; nt < 8; ++nt) {
            const int h2idx = nt * 4 + (lane & 3);    // half2 column index
            if (r0 < N_NODES)
                g_h0[(size_t)r0 * 32 + h2idx] =
                    __floats2half2_rn(d[rt][nt][0] + bias2[nt].x,
                                      d[rt][nt][1] + bias2[nt].y);
            if (r1 < N_NODES)
                g_h0[(size_t)r1 * 32 + h2idx] =
                    __floats2half2_rn(d[rt][nt][2] + bias2[nt].x,
                                      d[rt][nt][3] + bias2[nt].y);
        }
    }
}

__device__ __forceinline__ float2 h2f(__half2 h) { return __half22float2(h); }

// ---------------------------------------------------------------------------
// 5) Propagation: one warp per node; lane owns cols (2*lane, 2*lane+1).
//    new[t] = (deg>0) ? (in[t] + sum in[src[e]]) / (deg+1) : 0
//    stage 0: g_h0 -> g_h1 (fp16);  stage 1: g_h1 -> d_out (fp32, ReLU)
// ---------------------------------------------------------------------------
__global__ __launch_bounds__(256) void prop_kernel(float* __restrict__ dout, int stage) {
    const int gw   = (blockIdx.x * blockDim.x + threadIdx.x) >> 5;
    const int lane = threadIdx.x & 31;
    if (gw >= N_NODES) return;
    const int t = gw;

    const __half2* __restrict__ in = (stage == 0) ? g_h0 : g_h1;

    const int start = g_rowptr[t];
    const int end   = g_rowptr[t + 1];
    const int deg   = end - start;

    if (deg == 0) {
        if (stage == 0) g_h1[(size_t)t * 32 + lane] = __floats2half2_rn(0.f, 0.f);
        else            ((float2*)dout)[(size_t)t * 32 + lane] = make_float2(0.f, 0.f);
        return;
    }

    float2 acc = make_float2(0.f, 0.f);
    int e = start;
    for (; e + 4 <= end; e += 4) {
        const int s0 = __ldg(&g_src32[e + 0]);
        const int s1 = __ldg(&g_src32[e + 1]);
        const int s2 = __ldg(&g_src32[e + 2]);
        const int s3 = __ldg(&g_src32[e + 3]);
        const float2 v0 = h2f(in[(size_t)s0 * 32 + lane]);
        const float2 v1 = h2f(in[(size_t)s1 * 32 + lane]);
        const float2 v2 = h2f(in[(size_t)s2 * 32 + lane]);
        const float2 v3 = h2f(in[(size_t)s3 * 32 + lane]);
        acc.x += (v0.x + v1.x) + (v2.x + v3.x);
        acc.y += (v0.y + v1.y) + (v2.y + v3.y);
    }
    for (; e < end; ++e) {
        const int s = __ldg(&g_src32[e]);
        const float2 v = h2f(in[(size_t)s * 32 + lane]);
        acc.x += v.x; acc.y += v.y;
    }

    const float2 own = h2f(in[(size_t)t * 32 + lane]);
    const float sc = 1.0f / (float)(deg + 1);
    float2 r = make_float2((acc.x + own.x) * sc, (acc.y + own.y) * sc);
    if (stage == 0) {
        g_h1[(size_t)t * 32 + lane] = __floats2half2_rn(r.x, r.y);
    } else {
        r.x = fmaxf(r.x, 0.f); r.y = fmaxf(r.y, 0.f);
        ((float2*)dout)[(size_t)t * 32 + lane] = r;
    }
}

// ---------------------------------------------------------------------------
// Launch. Inputs (metadata order): data, W, b, src_idx, tgt_idx
// ---------------------------------------------------------------------------
extern "C" void kernel_launch(void* const* d_in, const int* in_sizes, int n_in,
                              void* d_out, int out_size) {
    const float* X = (const float*)d_in[0];
    const float* W = (const float*)d_in[1];
    const float* b = (const float*)d_in[2];
    const void*  src = d_in[3];
    const void*  tgt = d_in[4];
    float* out = (float*)d_out;

    detect_kernel<<<1, 32>>>(src);
    convert_kernel<<<(N_EDGES + 255) / 256, 256>>>(src, tgt);
    rowptr_kernel<<<(N_NODES + 1 + 255) / 256, 256>>>();
    gemm_kernel<<<(N_NODES + 127) / 128, 128>>>(X, W, b);
    const int propBlocks = (N_NODES * 32 + 255) / 256;  // 1 warp/node
    prop_kernel<<<propBlocks, 256>>>(out, 0);
    prop_kernel<<<propBlocks, 256>>>(out, 1);
}

// round 9
// speedup vs baseline: 2.1780x; 1.0231x over previous
#include <cuda_runtime.h>
#include <cuda_fp16.h>
#include <cstdint>

// Problem constants (fixed by the dataset)
#define N_NODES 100000
#define N_EDGES 800000
#define IN_SIZE 128
#define OUT_SIZE 64

// ---------------------------------------------------------------------------
// Scratch (no cudaMalloc allowed)
// ---------------------------------------------------------------------------
__device__ int   g_is64;
__device__ int   g_src32[N_EDGES];
__device__ int   g_tgt32[N_EDGES];
__device__ int   g_rowptr[N_NODES + 1];
// fp16 intermediate activations: [node][32] half2  (64 cols)
__device__ __align__(16) __half2 g_h0[(size_t)N_NODES * 32];
__device__ __align__(16) __half2 g_h1[(size_t)N_NODES * 32];

// ---------------------------------------------------------------------------
// 1) Detect int64 vs int32 indices (warp-parallel, one ballot).
// ---------------------------------------------------------------------------
__global__ void detect_kernel(const void* src_any) {
    const long long v = ((const long long*)src_any)[threadIdx.x & 31];
    const bool ok = (v >= 0 && v < (long long)N_NODES);
    const unsigned m = __ballot_sync(0xffffffffu, ok);
    if (threadIdx.x == 0) g_is64 = (m == 0xffffffffu) ? 1 : 0;
}

// ---------------------------------------------------------------------------
// 2) Normalize indices to int32 scratch.
// ---------------------------------------------------------------------------
__global__ void convert_kernel(const void* src_any, const void* tgt_any) {
    int i = blockIdx.x * blockDim.x + threadIdx.x;
    if (i >= N_EDGES) return;
    if (g_is64) {
        g_src32[i] = (int)((const long long*)src_any)[i];
        g_tgt32[i] = (int)((const long long*)tgt_any)[i];
    } else {
        g_src32[i] = ((const int*)src_any)[i];
        g_tgt32[i] = ((const int*)tgt_any)[i];
    }
}

// ---------------------------------------------------------------------------
// 3) row_ptr via per-node lower_bound in the sorted tgt array.
// ---------------------------------------------------------------------------
__global__ void rowptr_kernel() {
    int t = blockIdx.x * blockDim.x + threadIdx.x;
    if (t > N_NODES) return;
    int lo = 0, hi = N_EDGES;
    while (lo < hi) {
        int mid = (lo + hi) >> 1;
        if (g_tgt32[mid] < t) lo = mid + 1; else hi = mid;
    }
    g_rowptr[t] = lo;
}

// ---------------------------------------------------------------------------
// 4) GEMM via HMMA tensor cores: Y = X @ W + b -> fp16 store.
//    (unchanged from R7: measured 19.0us)
// ---------------------------------------------------------------------------
#define XS_HALVES (128 * 128)   // 32768 B
#define WS_HALVES (128 * 64)    // 16384 B

__global__ __launch_bounds__(128) void gemm_kernel(const float* __restrict__ X,
                                                   const float* __restrict__ W,
                                                   const float* __restrict__ b) {
    __shared__ __half Xs[XS_HALVES];   // [row][k], swizzled chunks
    __shared__ __half Ws[WS_HALVES];   // [k][n],  swizzled chunks

    const int tid    = threadIdx.x;
    const int lane   = tid & 31;
    const int warpId = tid >> 5;
    const int rowBase = blockIdx.x * 128;

    #pragma unroll
    for (int i = 0; i < 32; ++i) {
        const int linear = tid + 128 * i;
        const int row = linear >> 5;
        const int c   = linear & 31;
        const int gr  = rowBase + row;
        float4 v = (gr < N_NODES) ? __ldg((const float4*)&X[(size_t)gr * IN_SIZE + 4 * c])
                                  : make_float4(0.f, 0.f, 0.f, 0.f);
        __align__(8) __half2 h[2];
        h[0] = __floats2half2_rn(v.x, v.y);
        h[1] = __floats2half2_rn(v.z, v.w);
        const int chunk = ((c >> 1) ^ (row & 7));
        *(uint2*)&Xs[row * 128 + chunk * 8 + 4 * (c & 1)] = *(const uint2*)h;
    }

    #pragma unroll
    for (int i = 0; i < 16; ++i) {
        const int linear = tid + 128 * i;
        const int k = linear >> 4;
        const int c = linear & 15;
        float4 v = __ldg((const float4*)&W[(size_t)k * OUT_SIZE + 4 * c]);
        __align__(8) __half2 h[2];
        h[0] = __floats2half2_rn(v.x, v.y);
        h[1] = __floats2half2_rn(v.z, v.w);
        const int chunk = ((c >> 1) ^ (k & 7));
        *(uint2*)&Ws[k * 64 + chunk * 8 + 4 * (c & 1)] = *(const uint2*)h;
    }
    __syncthreads();

    const int wr = warpId * 32;
    float d[2][8][4];
    #pragma unroll
    for (int rt = 0; rt < 2; ++rt)
        #pragma unroll
        for (int nt = 0; nt < 8; ++nt)
            #pragma unroll
            for (int q = 0; q < 4; ++q) d[rt][nt][q] = 0.f;

    #pragma unroll
    for (int ks = 0; ks < 8; ++ks) {
        unsigned a[2][4];
        #pragma unroll
        for (int rt = 0; rt < 2; ++rt) {
            const int row = wr + rt * 16 + (lane & 15);
            const int chunk = (ks * 2 + (lane >> 4)) ^ (row & 7);
            const unsigned addr =
                (unsigned)__cvta_generic_to_shared(&Xs[row * 128 + chunk * 8]);
            asm volatile("ldmatrix.sync.aligned.m8n8.x4.shared.b16 {%0,%1,%2,%3}, [%4];"
                         : "=r"(a[rt][0]), "=r"(a[rt][1]), "=r"(a[rt][2]), "=r"(a[rt][3])
                         : "r"(addr));
        }
        #pragma unroll
        for (int np = 0; np < 4; ++np) {
            const int k = ks * 16 + (lane & 7) + ((lane >> 3) & 1) * 8;
            const int chunk = (np * 2 + (lane >> 4)) ^ (k & 7);
            const unsigned addr =
                (unsigned)__cvta_generic_to_shared(&Ws[k * 64 + chunk * 8]);
            unsigned bf[4];
            asm volatile("ldmatrix.sync.aligned.m8n8.x4.trans.shared.b16 {%0,%1,%2,%3}, [%4];"
                         : "=r"(bf[0]), "=r"(bf[1]), "=r"(bf[2]), "=r"(bf[3])
                         : "r"(addr));
            #pragma unroll
            for (int rt = 0; rt < 2; ++rt) {
                asm volatile(
                    "mma.sync.aligned.m16n8k16.row.col.f32.f16.f16.f32 "
                    "{%0,%1,%2,%3}, {%4,%5,%6,%7}, {%8,%9}, {%0,%1,%2,%3};"
                    : "+f"(d[rt][2 * np][0]), "+f"(d[rt][2 * np][1]),
                      "+f"(d[rt][2 * np][2]), "+f"(d[rt][2 * np][3])
                    : "r"(a[rt][0]), "r"(a[rt][1]), "r"(a[rt][2]), "r"(a[rt][3]),
                      "r"(bf[0]), "r"(bf[1]));
                asm volatile(
                    "mma.sync.aligned.m16n8k16.row.col.f32.f16.f16.f32 "
                    "{%0,%1,%2,%3}, {%4,%5,%6,%7}, {%8,%9}, {%0,%1,%2,%3};"
                    : "+f"(d[rt][2 * np + 1][0]), "+f"(d[rt][2 * np + 1][1]),
                      "+f"(d[rt][2 * np + 1][2]), "+f"(d[rt][2 * np + 1][3])
                    : "r"(a[rt][0]), "r"(a[rt][1]), "r"(a[rt][2]), "r"(a[rt][3]),
                      "r"(bf[2]), "r"(bf[3]));
            }
        }
    }

    float2 bias2[8];
    #pragma unroll
    for (int nt = 0; nt < 8; ++nt)
        bias2[nt] = __ldg(&((const float2*)b)[nt * 4 + (lane & 3)]);

    #pragma unroll
    for (int rt = 0; rt < 2; ++rt) {
        const int r0 = rowBase + wr + rt * 16 + (lane >> 2);
        const int r1 = r0 + 8;
        #pragma unroll
        for (int nt = 0; nt < 8; ++nt) {
            const int h2idx = nt * 4 + (lane & 3);
            if (r0 < N_NODES)
                g_h0[(size_t)r0 * 32 + h2idx] =
                    __floats2half2_rn(d[rt][nt][0] + bias2[nt].x,
                                      d[rt][nt][1] + bias2[nt].y);
            if (r1 < N_NODES)
                g_h0[(size_t)r1 * 32 + h2idx] =
                    __floats2half2_rn(d[rt][nt][2] + bias2[nt].x,
                                      d[rt][nt][3] + bias2[nt].y);
        }
    }
}

// accumulate 4 halves (one uint2) into a float4
__device__ __forceinline__ void acc8(float4& a, uint2 u) {
    const __half2 h0 = *reinterpret_cast<__half2*>(&u.x);
    const __half2 h1 = *reinterpret_cast<__half2*>(&u.y);
    const float2 f0 = __half22float2(h0);
    const float2 f1 = __half22float2(h1);
    a.x += f0.x; a.y += f0.y; a.z += f1.x; a.w += f1.y;
}

// ---------------------------------------------------------------------------
// 5) Propagation: one warp per node, TWO edges per load instruction.
//    Half-warp h (lanes h*16..h*16+15) processes edges start+h, start+h+2, ...
//    Each lane loads uint2 (4 halves) of its edge row -> 2 edge rows per
//    warp-instruction. shfl.xor(16) merges halves; lanes 0-15 store.
//    new[t] = (deg>0) ? (in[t] + sum in[src[e]]) / (deg+1) : 0
//    stage 0: g_h0 -> g_h1 (fp16);  stage 1: g_h1 -> d_out (fp32, ReLU)
// ---------------------------------------------------------------------------
__global__ __launch_bounds__(256) void prop_kernel(float* __restrict__ dout, int stage) {
    const int gw   = (blockIdx.x * blockDim.x + threadIdx.x) >> 5;
    const int lane = threadIdx.x & 31;
    if (gw >= N_NODES) return;
    const int t   = gw;
    const int sub  = lane & 15;     // column group: halves sub*4 .. sub*4+3
    const int half = lane >> 4;     // 0 = even edges, 1 = odd edges

    const __half2* __restrict__ in = (stage == 0) ? g_h0 : g_h1;

    const int start = g_rowptr[t];
    const int end   = g_rowptr[t + 1];
    const int deg   = end - start;

    if (deg == 0) {
        if (half == 0) {
            if (stage == 0) *(uint2*)&g_h1[(size_t)t * 32 + sub * 2] = make_uint2(0u, 0u);
            else            *(float4*)&dout[(size_t)t * 64 + sub * 4] =
                                make_float4(0.f, 0.f, 0.f, 0.f);
        }
        return;
    }

    float4 acc = make_float4(0.f, 0.f, 0.f, 0.f);
    int e = start + half;
    // 2 edges per half-warp in flight (4 per warp)
    for (; e + 2 < end; e += 4) {
        const int s0 = __ldg(&g_src32[e]);
        const int s1 = __ldg(&g_src32[e + 2]);
        const uint2 u0 = __ldg((const uint2*)&in[(size_t)s0 * 32 + sub * 2]);
        const uint2 u1 = __ldg((const uint2*)&in[(size_t)s1 * 32 + sub * 2]);
        acc8(acc, u0);
        acc8(acc, u1);
    }
    for (; e < end; e += 2) {
        const int s = __ldg(&g_src32[e]);
        const uint2 u = __ldg((const uint2*)&in[(size_t)s * 32 + sub * 2]);
        acc8(acc, u);
    }

    // merge the two half-warps (both halves end with the full sum)
    acc.x += __shfl_xor_sync(0xffffffffu, acc.x, 16);
    acc.y += __shfl_xor_sync(0xffffffffu, acc.y, 16);
    acc.z += __shfl_xor_sync(0xffffffffu, acc.z, 16);
    acc.w += __shfl_xor_sync(0xffffffffu, acc.w, 16);

    // own contribution + scale
    const uint2 uo = __ldg((const uint2*)&in[(size_t)t * 32 + sub * 2]);
    acc8(acc, uo);
    const float sc = 1.0f / (float)(deg + 1);
    acc.x *= sc; acc.y *= sc; acc.z *= sc; acc.w *= sc;

    if (half == 0) {
        if (stage == 0) {
            __align__(8) __half2 h[2];
            h[0] = __floats2half2_rn(acc.x, acc.y);
            h[1] = __floats2half2_rn(acc.z, acc.w);
            *(uint2*)&g_h1[(size_t)t * 32 + sub * 2] = *(const uint2*)h;
        } else {
            acc.x = fmaxf(acc.x, 0.f); acc.y = fmaxf(acc.y, 0.f);
            acc.z = fmaxf(acc.z, 0.f); acc.w = fmaxf(acc.w, 0.f);
            *(float4*)&dout[(size_t)t * 64 + sub * 4] = acc;
        }
    }
}

// ---------------------------------------------------------------------------
// Launch. Inputs (metadata order): data, W, b, src_idx, tgt_idx
// ---------------------------------------------------------------------------
extern "C" void kernel_launch(void* const* d_in, const int* in_sizes, int n_in,
                              void* d_out, int out_size) {
    const float* X = (const float*)d_in[0];
    const float* W = (const float*)d_in[1];
    const float* b = (const float*)d_in[2];
    const void*  src = d_in[3];
    const void*  tgt = d_in[4];
    float* out = (float*)d_out;

    detect_kernel<<<1, 32>>>(src);
    convert_kernel<<<(N_EDGES + 255) / 256, 256>>>(src, tgt);
    rowptr_kernel<<<(N_NODES + 1 + 255) / 256, 256>>>();
    gemm_kernel<<<(N_NODES + 127) / 128, 128>>>(X, W, b);
    const int propBlocks = (N_NODES * 32 + 255) / 256;  // 1 warp/node
    prop_kernel<<<propBlocks, 256>>>(out, 0);
    prop_kernel<<<propBlocks, 256>>>(out, 1);
}